// round 11
// baseline (speedup 1.0000x reference)
#include <cuda_runtime.h>
#include <cstdint>
#include <cstddef>

#define B_   128
#define T_   512
#define H_   256
#define G4_  1024

// recurrence geometry: 16 independent groups x 16 CTAs, 8 rows/group, 16 h-cols/CTA
#define NG   16
#define GC   16
// smem: Us2 [256 k][16 j] ulonglong2 = 64KB | hs2 u64[8][258] | comb ulonglong2[128] | base
#define OFF_HS   65536
#define HS2_STR  258
#define OFF_COMB (OFF_HS + 8*HS2_STR*8)
#define OFF_BASE (OFF_COMB + 128*16)
#define REC_SMEM (OFF_BASE + 32)

// ---------------- scratch (device globals; no allocation allowed) ----------------
__device__ float g_xz[(size_t)B_ * T_ * G4_];    // gate pre-activations (reused per layer)
__device__ float g_hseq[(size_t)B_ * T_ * H_];   // per-layer hidden sequence (also h-exchange)
__device__ unsigned int g_flag[NG * 32];         // per-CTA step flags; 128B line per group

// ---------------- packed f32x2 helpers (sm_103a FFMA2) ----------------
static __device__ __forceinline__ unsigned long long f2pack(float a, float b) {
    unsigned long long r;
    asm("mov.b64 %0, {%1, %2};" : "=l"(r) : "r"(__float_as_uint(a)), "r"(__float_as_uint(b)));
    return r;
}
static __device__ __forceinline__ void f2unpack(unsigned long long v, float& a, float& b) {
    unsigned int x, y;
    asm("mov.b64 {%0, %1}, %2;" : "=r"(x), "=r"(y) : "l"(v));
    a = __uint_as_float(x); b = __uint_as_float(y);
}
static __device__ __forceinline__ unsigned long long f2fma(
    unsigned long long a, unsigned long long b, unsigned long long c) {
    unsigned long long d;
    asm("fma.rn.f32x2 %0, %1, %2, %3;" : "=l"(d) : "l"(a), "l"(b), "l"(c));
    return d;
}
static __device__ __forceinline__ unsigned long long f2add(
    unsigned long long a, unsigned long long b) {
    unsigned long long d;
    asm("add.rn.f32x2 %0, %1, %2;" : "=l"(d) : "l"(a), "l"(b));
    return d;
}

// fast activations (rel err ~1e-6; tolerance 1e-3)
static __device__ __forceinline__ float sig_f(float x) {
    return __fdividef(1.f, 1.f + __expf(-x));
}
static __device__ __forceinline__ float tanh_f(float x) {
    return __fdividef(2.f, 1.f + __expf(-2.f * x)) - 1.f;
}

// ---------------- GEMM: C[M,N] = A[M,256] @ Bw[256,N] + bias (+tanh) ----------------
// BM=128, BN=128, BK=16, 256 threads, 8x8/thread, As pre-duplicated (a,a) u64.
template <bool TANH>
__global__ __launch_bounds__(256, 2) void gemm_bias(
    const float* __restrict__ A, const float* __restrict__ Bw,
    const float* __restrict__ bias, float* __restrict__ C, int N)
{
    __shared__ unsigned long long As2[16][130];
    __shared__ float Bs[16][132];
    const int tid = threadIdx.x;
    const int m0 = blockIdx.y * 128;
    const int n0 = blockIdx.x * 128;
    const int tr = tid >> 4;
    const int tc = tid & 15;

    unsigned long long acc[8][4];
#pragma unroll
    for (int i = 0; i < 8; i++)
#pragma unroll
        for (int p = 0; p < 4; p++) acc[i][p] = 0ULL;

    for (int k0 = 0; k0 < 256; k0 += 16) {
#pragma unroll
        for (int s = 0; s < 2; s++) {
            int e = tid + s * 256;
            int row = e >> 2, q = e & 3;
            float4 v = *(const float4*)&A[(size_t)(m0 + row) * 256 + k0 + q * 4];
            As2[q * 4 + 0][row] = f2pack(v.x, v.x);
            As2[q * 4 + 1][row] = f2pack(v.y, v.y);
            As2[q * 4 + 2][row] = f2pack(v.z, v.z);
            As2[q * 4 + 3][row] = f2pack(v.w, v.w);
        }
#pragma unroll
        for (int s = 0; s < 2; s++) {
            int e = tid + s * 256;
            int krow = e >> 5, nq = e & 31;
            *(float4*)&Bs[krow][nq * 4] =
                *(const float4*)&Bw[(size_t)(k0 + krow) * N + n0 + nq * 4];
        }
        __syncthreads();
#pragma unroll
        for (int kk = 0; kk < 16; kk++) {
            ulonglong2 a0 = *(const ulonglong2*)&As2[kk][tr * 8 + 0];
            ulonglong2 a1 = *(const ulonglong2*)&As2[kk][tr * 8 + 2];
            ulonglong2 a2 = *(const ulonglong2*)&As2[kk][tr * 8 + 4];
            ulonglong2 a3 = *(const ulonglong2*)&As2[kk][tr * 8 + 6];
            ulonglong2 b0 = *(const ulonglong2*)&Bs[kk][tc * 8 + 0];
            ulonglong2 b1 = *(const ulonglong2*)&Bs[kk][tc * 8 + 4];
            unsigned long long ap[8] = {a0.x, a0.y, a1.x, a1.y, a2.x, a2.y, a3.x, a3.y};
            unsigned long long bp[4] = {b0.x, b0.y, b1.x, b1.y};
#pragma unroll
            for (int i = 0; i < 8; i++)
#pragma unroll
                for (int p = 0; p < 4; p++)
                    acc[i][p] = f2fma(ap[i], bp[p], acc[i][p]);
        }
        __syncthreads();
    }

    float4 bv0 = *(const float4*)&bias[n0 + tc * 8];
    float4 bv1 = *(const float4*)&bias[n0 + tc * 8 + 4];
#pragma unroll
    for (int i = 0; i < 8; i++) {
        float c0, c1, c2, c3, c4, c5, c6, c7;
        f2unpack(acc[i][0], c0, c1);
        f2unpack(acc[i][1], c2, c3);
        f2unpack(acc[i][2], c4, c5);
        f2unpack(acc[i][3], c6, c7);
        c0 += bv0.x; c1 += bv0.y; c2 += bv0.z; c3 += bv0.w;
        c4 += bv1.x; c5 += bv1.y; c6 += bv1.z; c7 += bv1.w;
        if (TANH) {
            c0 = tanh_f(c0); c1 = tanh_f(c1); c2 = tanh_f(c2); c3 = tanh_f(c3);
            c4 = tanh_f(c4); c5 = tanh_f(c5); c6 = tanh_f(c6); c7 = tanh_f(c7);
        }
        float* cp = &C[(size_t)(m0 + tr * 8 + i) * N + n0 + tc * 8];
        *(float4*)cp = make_float4(c0, c1, c2, c3);
        *(float4*)(cp + 4) = make_float4(c4, c5, c6, c7);
    }
}

// ---------------- persistent LSTM recurrence (v8: barrier-free flag sync) ----------------
// 256 CTAs; 16 groups x 16 CTAs; group = 8 batch rows, CTA = 16 h-cols.
// No group barrier: producers publish per-CTA monotonic flags (fence + volatile store);
// consumers poll the 16 flags of their group and read h straight from L2-hot hseq.
__global__ __launch_bounds__(256, 2) void lstm_rec(
    const float* __restrict__ xz, const float* __restrict__ U, float* __restrict__ hseq)
{
    extern __shared__ unsigned char sraw[];
    ulonglong2* Us2 = (ulonglong2*)sraw;                             // [256 k][16 j]
    unsigned long long* hs2 = (unsigned long long*)(sraw + OFF_HS);  // [8 r][258 k] (h,h)
    ulonglong2* comb = (ulonglong2*)(sraw + OFF_COMB);               // [128]
    unsigned int* sbase = (unsigned int*)(sraw + OFF_BASE);

    const int tid = threadIdx.x;
    const int cta = blockIdx.x;
    const int grp = cta >> 4;            // 0..15
    const int slot = cta & 15;           // CTA within group
    const int r0 = grp * 8;              // batch rows
    const int j0 = slot * 16;            // h columns
    const int w = tid >> 5;
    const int lane = tid & 31;
    const int kh = w >> 2;               // k-half
    const int r = lane >> 2;             // 0..7
    const int j = (w & 3) * 4 + (lane & 3);  // 0..15
    const int cell = j * 8 + r;          // 0..127

    // Load U slice once: Us2[k*16+j] = {(U[k][i],U[k][f]), (U[k][g],U[k][o])}
    for (int e = tid; e < 4096; e += 256) {
        int k = e >> 4, jj = e & 15;
        const float* up = U + (size_t)k * G4_ + j0 + jj;
        ulonglong2 v;
        v.x = f2pack(up[0], up[256]);
        v.y = f2pack(up[512], up[768]);
        Us2[e] = v;
    }
    // Zero duplicated h tile (h(-1) = 0)
    for (int e = tid; e < 8 * HS2_STR; e += 256) hs2[e] = 0ULL;
    // Read own flag as per-launch base (all flags equal at launch boundaries)
    if (tid == 0) *sbase = *(volatile unsigned int*)&g_flag[grp * 32 + slot];

    // Prime xz pipeline for t=0 (kh==0 threads own the cells)
    float cz0 = 0.f, cz1 = 0.f, cz2 = 0.f, cz3 = 0.f;
    if (kh == 0) {
        const float* xp = xz + (size_t)(r0 + r) * T_ * G4_ + j0 + j;
        cz0 = __ldcs(xp);
        cz1 = __ldcs(xp + 256);
        cz2 = __ldcs(xp + 512);
        cz3 = __ldcs(xp + 768);
    }
    __syncthreads();
    const unsigned int base = *sbase;

    float c = 0.f;
    const unsigned long long* hp = hs2 + (size_t)r * HS2_STR + kh * 128;
    const ulonglong2* up2 = Us2 + (size_t)(kh * 128) * 16 + j;

    for (int t = 0; t < T_; ++t) {
        if (t > 0) {
            // Wait for all 16 producer flags of this group to reach base + t
            if (w == 0) {
                if (lane < 16) {
                    const volatile unsigned int* fp = &g_flag[grp * 32 + lane];
                    unsigned int tgt = base + (unsigned int)t;
                    while (*fp < tgt) { }
                }
                __syncwarp();
                if (lane == 0) __threadfence();   // acquire: order h loads after flag observe
            }
            __syncthreads();
            // Load h(t-1) tile [8 x 256] from L2-hot hseq; store duplicated (h,h)
#pragma unroll
            for (int i = 0; i < 2; i++) {
                int e = tid + i * 256;
                int rr = e >> 6, cc = (e & 63) * 4;
                float4 v = __ldcg((const float4*)&hseq[((size_t)(r0 + rr) * T_ + (t - 1)) * H_ + cc]);
                unsigned long long* d = hs2 + (size_t)rr * HS2_STR + cc;
                d[0] = f2pack(v.x, v.x);
                d[1] = f2pack(v.y, v.y);
                d[2] = f2pack(v.z, v.z);
                d[3] = f2pack(v.w, v.w);
            }
            __syncthreads();
        }

        // Init accumulators with gate pre-activations, then prefetch next step's xz
        unsigned long long aA0 = (kh == 0) ? f2pack(cz0, cz1) : 0ULL;
        unsigned long long aB0 = (kh == 0) ? f2pack(cz2, cz3) : 0ULL;
        unsigned long long aA1 = 0ULL, aB1 = 0ULL;
        if (kh == 0 && t + 1 < T_) {
            const float* xp = xz + ((size_t)(r0 + r) * T_ + (t + 1)) * G4_ + j0 + j;
            cz0 = __ldcs(xp);
            cz1 = __ldcs(xp + 256);
            cz2 = __ldcs(xp + 512);
            cz3 = __ldcs(xp + 768);
        }

        // Inner loop: LDS.64 (h,h) + LDS.128 (u quad) + 2 FFMA2 per k
#pragma unroll 8
        for (int k = 0; k < 128; k += 2) {
            {
                unsigned long long hh = hp[k];
                ulonglong2 u = up2[(size_t)k * 16];
                aA0 = f2fma(hh, u.x, aA0); aB0 = f2fma(hh, u.y, aB0);
            }
            {
                unsigned long long hh = hp[k + 1];
                ulonglong2 u = up2[(size_t)(k + 1) * 16];
                aA1 = f2fma(hh, u.x, aA1); aB1 = f2fma(hh, u.y, aB1);
            }
        }
        unsigned long long accA = f2add(aA0, aA1);
        unsigned long long accB = f2add(aB0, aB1);
        if (kh == 1) comb[cell] = make_ulonglong2(accA, accB);
        __syncthreads();

        if (kh == 0) {
            ulonglong2 p = comb[cell];
            accA = f2add(accA, p.x);
            accB = f2add(accB, p.y);
            float azi, azf, azg, azo;
            f2unpack(accA, azi, azf);
            f2unpack(accB, azg, azo);
            float ig = sig_f(azi);
            float fg = sig_f(azf);
            float gg = tanh_f(azg);
            float og = sig_f(azo);
            c = fg * c + ig * gg;
            float h = og * tanh_f(c);
            __stcg(&hseq[((size_t)(r0 + r) * T_ + t) * H_ + j0 + j], h);
        }
        __syncthreads();   // all h stores issued before flag publish
        if (tid == 0) {
            __threadfence();   // release: h stores visible before flag
            *(volatile unsigned int*)&g_flag[grp * 32 + slot] = base + (unsigned int)(t + 1);
        }
    }
}

// ---------------- LayerNorm over last dim (256), one warp per row ----------------
__global__ __launch_bounds__(256) void ln_kernel(
    const float* __restrict__ X, const float* __restrict__ gamma,
    const float* __restrict__ beta, float* __restrict__ out)
{
    int w = threadIdx.x >> 5, lane = threadIdx.x & 31;
    size_t row = (size_t)blockIdx.x * 8 + w;
    const float* x = X + row * 256;
    float4 v0 = *(const float4*)&x[lane * 4];
    float4 v1 = *(const float4*)&x[128 + lane * 4];
    float s = v0.x + v0.y + v0.z + v0.w + v1.x + v1.y + v1.z + v1.w;
    float q = v0.x * v0.x + v0.y * v0.y + v0.z * v0.z + v0.w * v0.w
            + v1.x * v1.x + v1.y * v1.y + v1.z * v1.z + v1.w * v1.w;
#pragma unroll
    for (int o = 16; o > 0; o >>= 1) {
        s += __shfl_xor_sync(0xFFFFFFFFu, s, o);
        q += __shfl_xor_sync(0xFFFFFFFFu, q, o);
    }
    float mu = s * (1.f / 256.f);
    float var = q * (1.f / 256.f) - mu * mu;
    float rstd = rsqrtf(var + 1e-3f);
    float4 g0 = *(const float4*)&gamma[lane * 4];
    float4 g1 = *(const float4*)&gamma[128 + lane * 4];
    float4 e0 = *(const float4*)&beta[lane * 4];
    float4 e1 = *(const float4*)&beta[128 + lane * 4];
    float4 o0, o1;
    o0.x = (v0.x - mu) * rstd * g0.x + e0.x;
    o0.y = (v0.y - mu) * rstd * g0.y + e0.y;
    o0.z = (v0.z - mu) * rstd * g0.z + e0.z;
    o0.w = (v0.w - mu) * rstd * g0.w + e0.w;
    o1.x = (v1.x - mu) * rstd * g1.x + e1.x;
    o1.y = (v1.y - mu) * rstd * g1.y + e1.y;
    o1.z = (v1.z - mu) * rstd * g1.z + e1.z;
    o1.w = (v1.w - mu) * rstd * g1.w + e1.w;
    float* op = out + row * 256;
    *(float4*)&op[lane * 4] = o0;
    *(float4*)&op[128 + lane * 4] = o1;
}

// ---------------- entry point ----------------
extern "C" void kernel_launch(void* const* d_in, const int* in_sizes, int n_in,
                              void* d_out, int out_size)
{
    const float* x  = (const float*)d_in[0];
    const float* W0 = (const float*)d_in[1];
    const float* U0 = (const float*)d_in[2];
    const float* b0 = (const float*)d_in[3];
    const float* W1 = (const float*)d_in[4];
    const float* U1 = (const float*)d_in[5];
    const float* b1 = (const float*)d_in[6];
    const float* Wd = (const float*)d_in[7];
    const float* bd = (const float*)d_in[8];
    const float* ga = (const float*)d_in[9];
    const float* be = (const float*)d_in[10];
    float* out = (float*)d_out;

    float *xz, *hseq;
    cudaGetSymbolAddress((void**)&xz, g_xz);
    cudaGetSymbolAddress((void**)&hseq, g_hseq);
    cudaFuncSetAttribute(lstm_rec, cudaFuncAttributeMaxDynamicSharedMemorySize, REC_SMEM);

    // Layer 0
    gemm_bias<false><<<dim3(8, 512), 256>>>(x, W0, b0, xz, G4_);
    lstm_rec<<<256, 256, REC_SMEM>>>(xz, U0, hseq);
    // Layer 1
    gemm_bias<false><<<dim3(8, 512), 256>>>(hseq, W1, b1, xz, G4_);
    lstm_rec<<<256, 256, REC_SMEM>>>(xz, U1, hseq);
    // Dense + tanh (into g_xz scratch), then LayerNorm
    gemm_bias<true><<<dim3(2, 512), 256>>>(hseq, Wd, bd, xz, H_);
    ln_kernel<<<8192, 256>>>(xz, ga, be, out);
}